// round 2
// baseline (speedup 1.0000x reference)
#include <cuda_runtime.h>

#define B_ 64
#define J_ 25
#define V_ 50000
#define VT 128          // vertices per block (= threads)
#define NB 8            // batches per block
#define NPAIR (NB/2)

// Scratch (device globals; no allocation allowed)
__device__ float g_L[B_*J_*12];   // per-(b,j) local affine (3x4 row-major)
__device__ float g_T[B_*J_*12];   // per-(b,j) skinning transform (3x4 row-major)

// ---------------------------------------------------------------------------
// Fused FK kernel (single block):
// Phase 1 (1024 threads): local = (local_pose with t += skel_corr) @ euler2mat
// Phase 2 (192 threads): sequential chain -> G, T = G @ gpi, joint_out.
// __syncthreads() orders the g_L global round-trip within the block.
// ---------------------------------------------------------------------------
__global__ void fk_kernel(const float* __restrict__ je,
                          const float* __restrict__ lp,
                          const float* __restrict__ sc,
                          const float* __restrict__ gpi,
                          const int* __restrict__ parents,
                          float* __restrict__ joint_out) {
    int tid = threadIdx.x;

    for (int idx = tid; idx < B_ * J_; idx += blockDim.x) {
        int j = idx % J_;
        float ex = je[idx*3+0], ey = je[idx*3+1], ez = je[idx*3+2];
        float sx, cx, sy, cy, sz, cz;
        sincosf(ex, &sx, &cx);
        sincosf(ey, &sy, &cy);
        sincosf(ez, &sz, &cz);
        float R00 = cz*cy, R01 = cz*sy*sx - sz*cx, R02 = cz*sy*cx + sz*sx;
        float R10 = sz*cy, R11 = sz*sy*sx + cz*cx, R12 = sz*sy*cx - cz*sx;
        float R20 = -sy,   R21 = cy*sx,            R22 = cy*cx;
        const float* L0 = lp + j*16;
        float* out = g_L + idx*12;
        #pragma unroll
        for (int r = 0; r < 3; ++r) {
            float a0 = L0[r*4+0], a1 = L0[r*4+1], a2 = L0[r*4+2];
            out[r*4+0] = a0*R00 + a1*R10 + a2*R20;
            out[r*4+1] = a0*R01 + a1*R11 + a2*R21;
            out[r*4+2] = a0*R02 + a1*R12 + a2*R22;
            out[r*4+3] = L0[r*4+3] + sc[j*3+r];
        }
    }

    __syncthreads();

    if (tid >= B_ * 3) return;
    int b = tid / 3, r = tid % 3;
    float Grow[J_][4];
    float pr0 = 0.f, pr1 = 0.f, pr2 = 0.f, pr3 = 0.f;
    int prevj = -2;
    for (int j = 0; j < J_; ++j) {
        int pj = parents[j];
        float g0, g1, g2, g3;
        if (pj < 0) {
            g0 = (r == 0) ? 1.f : 0.f;
            g1 = (r == 1) ? 1.f : 0.f;
            g2 = (r == 2) ? 1.f : 0.f;
            g3 = 0.f;
        } else {
            float p0, p1, p2, p3;
            if (pj == prevj) { p0 = pr0; p1 = pr1; p2 = pr2; p3 = pr3; }
            else { p0 = Grow[pj][0]; p1 = Grow[pj][1]; p2 = Grow[pj][2]; p3 = Grow[pj][3]; }
            const float* L = g_L + (b*J_ + j) * 12;
            g0 = p0*L[0] + p1*L[4] + p2*L[8];
            g1 = p0*L[1] + p1*L[5] + p2*L[9];
            g2 = p0*L[2] + p1*L[6] + p2*L[10];
            g3 = p0*L[3] + p1*L[7] + p2*L[11] + p3;
        }
        Grow[j][0] = g0; Grow[j][1] = g1; Grow[j][2] = g2; Grow[j][3] = g3;
        pr0 = g0; pr1 = g1; pr2 = g2; pr3 = g3; prevj = j;

        const float* P = gpi + j*16;
        float* T = g_T + (b*J_ + j) * 12 + r*4;
        T[0] = g0*P[0] + g1*P[4] + g2*P[8];
        T[1] = g0*P[1] + g1*P[5] + g2*P[9];
        T[2] = g0*P[2] + g1*P[6] + g2*P[10];
        T[3] = g0*P[3] + g1*P[7] + g2*P[11] + g3;
        joint_out[(b*J_ + j)*3 + r] = g3;
    }
}

// ---------------------------------------------------------------------------
// f32x2 packed helpers (sm_100+)
// ---------------------------------------------------------------------------
__device__ __forceinline__ unsigned long long pack2(float lo, float hi) {
    unsigned long long d;
    asm("mov.b64 %0, {%1, %2};" : "=l"(d)
        : "r"(__float_as_uint(lo)), "r"(__float_as_uint(hi)));
    return d;
}
__device__ __forceinline__ unsigned long long pack2s(float w) {
    unsigned long long d;
    asm("mov.b64 %0, {%1, %1};" : "=l"(d) : "r"(__float_as_uint(w)));
    return d;
}
__device__ __forceinline__ void unpack2(unsigned long long s, float& lo, float& hi) {
    unsigned int a, b;
    asm("mov.b64 {%0, %1}, %2;" : "=r"(a), "=r"(b) : "l"(s));
    lo = __uint_as_float(a); hi = __uint_as_float(b);
}
__device__ __forceinline__ void fma2acc(unsigned long long& d,
                                        unsigned long long a,
                                        unsigned long long b) {
    asm("fma.rn.f32x2 %0, %1, %2, %0;" : "+l"(d) : "l"(a), "l"(b));
}
__device__ __forceinline__ unsigned long long fma2(unsigned long long a,
                                                   unsigned long long b,
                                                   unsigned long long c) {
    unsigned long long d;
    asm("fma.rn.f32x2 %0, %1, %2, %3;" : "=l"(d) : "l"(a), "l"(b), "l"(c));
    return d;
}

// ---------------------------------------------------------------------------
// Kernel B: skinning. Block = 128-vertex tile x 8 batches (4 batch pairs).
// Weights staged coalesced into smem, re-read per joint (saves 25 regs ->
// 64-reg cap -> 8 blocks/SM = 32 warps). T per batch pair interleaved as
// float2 -> packed fma.rn.f32x2 does both batches per instruction.
// Next pair's pc/ic loads are prefetched across the current j-loop.
// ---------------------------------------------------------------------------
__global__ __launch_bounds__(VT, 8)
void skin_kernel(const float* __restrict__ vtx,
                 const float* __restrict__ W,
                 const float* __restrict__ pc,
                 const float* __restrict__ ic,
                 float* __restrict__ mesh_out) {
    __shared__ float ws[VT * J_];                       // 12.8 KB
    __shared__ __align__(16) float2 Ts[NPAIR * J_ * 12]; // 9.6 KB

    int tid = threadIdx.x;
    int v0 = blockIdx.x * VT;
    int b0base = blockIdx.y * NB;
    int nv = min(VT, V_ - v0);

    // Stage weights for this vertex tile (contiguous, coalesced)
    int nW = nv * J_;
    for (int i = tid; i < nW; i += VT)
        ws[i] = W[(size_t)v0 * J_ + i];

    // Stage T for NB batches, interleaved per batch pair
    for (int i = tid; i < NPAIR * J_ * 12; i += VT) {
        int p = i / (J_ * 12);
        int rem = i - p * (J_ * 12);
        int b0 = b0base + 2 * p;
        Ts[i] = make_float2(g_T[b0 * J_ * 12 + rem],
                            g_T[(b0 + 1) * J_ * 12 + rem]);
    }
    __syncthreads();

    if (tid >= nv) return;
    int v = v0 + tid;

    float vx = vtx[v*3+0], vy = vtx[v*3+1], vz = vtx[v*3+2];

    const size_t strideB = (size_t)V_ * 3;
    size_t base = ((size_t)b0base * V_ + v) * 3;

    // Prefetch pair 0 raw correctives
    float fpc[6], fic[6];
    {
        size_t o0 = base, o1 = base + strideB;
        #pragma unroll
        for (int k = 0; k < 3; ++k) {
            fpc[k]   = pc[o0 + k]; fic[k]   = ic[o0 + k];
            fpc[3+k] = pc[o1 + k]; fic[3+k] = ic[o1 + k];
        }
    }

    #pragma unroll 1
    for (int p = 0; p < NPAIR; ++p) {
        size_t o0 = base + (size_t)(2 * p) * strideB;
        size_t o1 = o0 + strideB;

        // combine current pair's coords
        unsigned long long ppx = pack2(vx + fpc[0] + fic[0], vx + fpc[3] + fic[3]);
        unsigned long long ppy = pack2(vy + fpc[1] + fic[1], vy + fpc[4] + fic[4]);
        unsigned long long ppz = pack2(vz + fpc[2] + fic[2], vz + fpc[5] + fic[5]);

        // prefetch next pair's raw correctives
        if (p < NPAIR - 1) {
            size_t n0 = o0 + 2 * strideB, n1 = n0 + strideB;
            #pragma unroll
            for (int k = 0; k < 3; ++k) {
                fpc[k]   = pc[n0 + k]; fic[k]   = ic[n0 + k];
                fpc[3+k] = pc[n1 + k]; fic[3+k] = ic[n1 + k];
            }
        }

        unsigned long long M2[12];
        #pragma unroll
        for (int k = 0; k < 12; ++k) M2[k] = 0ull;

        const ulonglong2* tbase =
            reinterpret_cast<const ulonglong2*>(Ts + p * J_ * 12);
        const float* wrow = ws + tid * J_;
        #pragma unroll
        for (int j = 0; j < J_; ++j) {
            unsigned long long w2 = pack2s(wrow[j]);
            const ulonglong2* trow = tbase + j * 6;   // 12 float2 = 6 x 16B
            #pragma unroll
            for (int m = 0; m < 6; ++m) {
                ulonglong2 q = trow[m];
                fma2acc(M2[2*m],     q.x, w2);
                fma2acc(M2[2*m + 1], q.y, w2);
            }
        }

        #pragma unroll
        for (int r = 0; r < 3; ++r) {
            unsigned long long o = M2[r*4 + 3];
            o = fma2(M2[r*4 + 0], ppx, o);
            o = fma2(M2[r*4 + 1], ppy, o);
            o = fma2(M2[r*4 + 2], ppz, o);
            float a, bb; unpack2(o, a, bb);
            mesh_out[o0 + r] = a;
            mesh_out[o1 + r] = bb;
        }
    }
}

// ---------------------------------------------------------------------------
extern "C" void kernel_launch(void* const* d_in, const int* in_sizes, int n_in,
                              void* d_out, int out_size) {
    const float* joint_euler = (const float*)d_in[0];
    const float* vtx         = (const float*)d_in[1];
    const float* W           = (const float*)d_in[2];
    const float* local_pose  = (const float*)d_in[3];
    const float* gpi         = (const float*)d_in[4];
    const float* sc          = (const float*)d_in[5];
    const float* pc          = (const float*)d_in[6];
    const float* ic          = (const float*)d_in[7];
    const int*   parents     = (const int*)d_in[8];
    float* out = (float*)d_out;

    fk_kernel<<<1, 1024>>>(joint_euler, local_pose, sc, gpi, parents, out);
    dim3 grid((V_ + VT - 1) / VT, B_ / NB);
    skin_kernel<<<grid, VT>>>(vtx, W, pc, ic, out + B_*J_*3);
}

// round 3
// speedup vs baseline: 2.1032x; 2.1032x over previous
#include <cuda_runtime.h>

#define B_ 64
#define J_ 25
#define V_ 50000
#define VT 128          // threads per skin block
#define VT2 256         // vertices per skin block (2 per thread)
#define NB 8            // batches per skin block
#define NPAIR (NB/2)
#define WSTR 258        // ws_t row stride (even -> 8B-aligned LDS.64, conflict-light)
#define BPB 32          // batches per fk block

// Scratch (device global; no allocation allowed)
__device__ float g_T[B_*J_*12];   // per-(b,j) skinning transform (3x4 row-major)

// ---------------------------------------------------------------------------
// FK kernel: 2 blocks x 1024 threads, 32 batches per block. Locals computed
// into static smem (38.4KB), then 96 threads run the sequential chain with
// smem-only reads. Emits g_T and joint_out.
// ---------------------------------------------------------------------------
__global__ __launch_bounds__(1024)
void fk_kernel(const float* __restrict__ je,
               const float* __restrict__ lp,
               const float* __restrict__ sc,
               const float* __restrict__ gpi,
               const int* __restrict__ parents,
               float* __restrict__ joint_out) {
    __shared__ float ls[BPB * J_ * 12];   // locals, 3x4 row-major
    __shared__ float gpis[J_ * 16];
    __shared__ int   par[J_];

    int tid = threadIdx.x;
    int bbase = blockIdx.x * BPB;

    if (tid < J_ * 16) gpis[tid] = gpi[tid];
    if (tid < J_) par[tid] = parents[tid];

    // Phase 1: local = (local_pose with t += skel_corr) @ euler2mat(joint_euler)
    for (int idx = tid; idx < BPB * J_; idx += blockDim.x) {
        int j = idx % J_;
        int gidx = bbase * J_ + idx;
        float ex = je[gidx*3+0], ey = je[gidx*3+1], ez = je[gidx*3+2];
        float sx, cx, sy, cy, sz, cz;
        sincosf(ex, &sx, &cx);
        sincosf(ey, &sy, &cy);
        sincosf(ez, &sz, &cz);
        float R00 = cz*cy, R01 = cz*sy*sx - sz*cx, R02 = cz*sy*cx + sz*sx;
        float R10 = sz*cy, R11 = sz*sy*sx + cz*cx, R12 = sz*sy*cx - cz*sx;
        float R20 = -sy,   R21 = cy*sx,            R22 = cy*cx;
        const float* L0 = lp + j*16;
        float* out = ls + idx*12;
        #pragma unroll
        for (int r = 0; r < 3; ++r) {
            float a0 = L0[r*4+0], a1 = L0[r*4+1], a2 = L0[r*4+2];
            out[r*4+0] = a0*R00 + a1*R10 + a2*R20;
            out[r*4+1] = a0*R01 + a1*R11 + a2*R21;
            out[r*4+2] = a0*R02 + a1*R12 + a2*R22;
            out[r*4+3] = L0[r*4+3] + sc[j*3+r];
        }
    }

    __syncthreads();

    // Phase 2: sequential chain, thread = (batch-local, row)
    if (tid >= BPB * 3) return;
    int bl = tid / 3, r = tid % 3;
    int b = bbase + bl;

    float Grow[J_][4];
    float pr0 = 0.f, pr1 = 0.f, pr2 = 0.f, pr3 = 0.f;
    int prevj = -2;
    for (int j = 0; j < J_; ++j) {
        int pj = par[j];
        float g0, g1, g2, g3;
        if (pj < 0) {
            g0 = (r == 0) ? 1.f : 0.f;
            g1 = (r == 1) ? 1.f : 0.f;
            g2 = (r == 2) ? 1.f : 0.f;
            g3 = 0.f;
        } else {
            float p0, p1, p2, p3;
            if (pj == prevj) { p0 = pr0; p1 = pr1; p2 = pr2; p3 = pr3; }
            else { p0 = Grow[pj][0]; p1 = Grow[pj][1]; p2 = Grow[pj][2]; p3 = Grow[pj][3]; }
            const float* L = ls + (bl*J_ + j) * 12;
            g0 = p0*L[0] + p1*L[4] + p2*L[8];
            g1 = p0*L[1] + p1*L[5] + p2*L[9];
            g2 = p0*L[2] + p1*L[6] + p2*L[10];
            g3 = p0*L[3] + p1*L[7] + p2*L[11] + p3;
        }
        Grow[j][0] = g0; Grow[j][1] = g1; Grow[j][2] = g2; Grow[j][3] = g3;
        pr0 = g0; pr1 = g1; pr2 = g2; pr3 = g3; prevj = j;

        const float* P = gpis + j*16;
        float4 t4;
        t4.x = g0*P[0] + g1*P[4] + g2*P[8];
        t4.y = g0*P[1] + g1*P[5] + g2*P[9];
        t4.z = g0*P[2] + g1*P[6] + g2*P[10];
        t4.w = g0*P[3] + g1*P[7] + g2*P[11] + g3;
        *reinterpret_cast<float4*>(g_T + (b*J_ + j)*12 + r*4) = t4;
        joint_out[(b*J_ + j)*3 + r] = g3;
    }
}

// ---------------------------------------------------------------------------
// f32x2 packed helpers (sm_100+)
// ---------------------------------------------------------------------------
__device__ __forceinline__ unsigned long long pack2(float lo, float hi) {
    unsigned long long d;
    asm("mov.b64 %0, {%1, %2};" : "=l"(d)
        : "r"(__float_as_uint(lo)), "r"(__float_as_uint(hi)));
    return d;
}
__device__ __forceinline__ unsigned long long pack2s(float w) {
    unsigned long long d;
    asm("mov.b64 %0, {%1, %1};" : "=l"(d) : "r"(__float_as_uint(w)));
    return d;
}
__device__ __forceinline__ void unpack2(unsigned long long s, float& lo, float& hi) {
    unsigned int a, b;
    asm("mov.b64 {%0, %1}, %2;" : "=r"(a), "=r"(b) : "l"(s));
    lo = __uint_as_float(a); hi = __uint_as_float(b);
}
__device__ __forceinline__ void fma2acc(unsigned long long& d,
                                        unsigned long long a,
                                        unsigned long long b) {
    asm("fma.rn.f32x2 %0, %1, %2, %0;" : "+l"(d) : "l"(a), "l"(b));
}
__device__ __forceinline__ unsigned long long fma2(unsigned long long a,
                                                   unsigned long long b,
                                                   unsigned long long c) {
    unsigned long long d;
    asm("fma.rn.f32x2 %0, %1, %2, %3;" : "=l"(d) : "l"(a), "l"(b), "l"(c));
    return d;
}

// ---------------------------------------------------------------------------
// Skinning kernel. 128 threads handle 256 vertices (2 adjacent per thread)
// x 8 batches (4 batch pairs). T staged per pair as interleaved float2 in
// smem; packed fma.rn.f32x2 covers both batches. Each T LDS.128 now feeds
// BOTH vertices (halves the LDS/vertex that bound round 2 at L1=73%).
// Weights transposed in smem -> one LDS.64 per (pair, joint).
// ---------------------------------------------------------------------------
__global__ __launch_bounds__(VT, 4)
void skin_kernel(const float* __restrict__ vtx,
                 const float* __restrict__ W,
                 const float* __restrict__ pc,
                 const float* __restrict__ ic,
                 float* __restrict__ mesh_out) {
    __shared__ float ws_t[J_ * WSTR];                     // 25.8 KB, transposed
    __shared__ __align__(16) float2 Ts[NPAIR * J_ * 12];  // 9.6 KB

    int tid = threadIdx.x;
    int v0 = blockIdx.x * VT2;
    int b0base = blockIdx.y * NB;
    int nv = min(VT2, V_ - v0);

    // Stage weights transposed: ws_t[j*WSTR + vv] = W[v0+vv][j]
    // (gmem read coalesced; smem store stride 258 -> ~2-way max conflicts)
    for (int i = tid; i < nv * J_; i += VT) {
        int vv = i / J_;
        int j  = i - vv * J_;
        ws_t[j * WSTR + vv] = W[(size_t)v0 * J_ + i];
    }
    // Stage T for NB batches, interleaved per batch pair
    for (int i = tid; i < NPAIR * J_ * 12; i += VT) {
        int p = i / (J_ * 12);
        int rem = i - p * (J_ * 12);
        int b0 = b0base + 2 * p;
        Ts[i] = make_float2(g_T[b0 * (J_*12) + rem],
                            g_T[(b0 + 1) * (J_*12) + rem]);
    }
    __syncthreads();

    int vA = v0 + 2 * tid;
    if (vA >= V_ || 2 * tid >= nv) return;
    // V_ is even and vA is even -> vB = vA+1 is always in-bounds.
    int vB = vA + 1;

    float vAx = vtx[vA*3+0], vAy = vtx[vA*3+1], vAz = vtx[vA*3+2];
    float vBx = vtx[vB*3+0], vBy = vtx[vB*3+1], vBz = vtx[vB*3+2];

    const size_t strideB = (size_t)V_ * 3;
    const size_t base = (size_t)b0base * strideB + (size_t)vA * 3;  // even offset

    #pragma unroll 1
    for (int p = 0; p < NPAIR; ++p) {
        size_t o0 = base + (size_t)(2 * p) * strideB;   // batch b0: [Ax Ay Az Bx By Bz]
        size_t o1 = o0 + strideB;                       // batch b1

        // Load correctives: 6 consecutive floats per (array,batch), 8B aligned
        float2 pc00 = *(const float2*)(pc + o0), pc01 = *(const float2*)(pc + o0 + 2),
               pc02 = *(const float2*)(pc + o0 + 4);
        float2 pc10 = *(const float2*)(pc + o1), pc11 = *(const float2*)(pc + o1 + 2),
               pc12 = *(const float2*)(pc + o1 + 4);
        float2 ic00 = *(const float2*)(ic + o0), ic01 = *(const float2*)(ic + o0 + 2),
               ic02 = *(const float2*)(ic + o0 + 4);
        float2 ic10 = *(const float2*)(ic + o1), ic11 = *(const float2*)(ic + o1 + 2),
               ic12 = *(const float2*)(ic + o1 + 4);

        // Packed per-vertex coords over the batch pair {b0, b1}
        unsigned long long ppxA = pack2(vAx + pc00.x + ic00.x, vAx + pc10.x + ic10.x);
        unsigned long long ppyA = pack2(vAy + pc00.y + ic00.y, vAy + pc10.y + ic10.y);
        unsigned long long ppzA = pack2(vAz + pc01.x + ic01.x, vAz + pc11.x + ic11.x);
        unsigned long long ppxB = pack2(vBx + pc01.y + ic01.y, vBx + pc11.y + ic11.y);
        unsigned long long ppyB = pack2(vBy + pc02.x + ic02.x, vBy + pc12.x + ic12.x);
        unsigned long long ppzB = pack2(vBz + pc02.y + ic02.y, vBz + pc12.y + ic12.y);

        unsigned long long MA[12], MB[12];
        #pragma unroll
        for (int k = 0; k < 12; ++k) { MA[k] = 0ull; MB[k] = 0ull; }

        const ulonglong2* tbase =
            reinterpret_cast<const ulonglong2*>(Ts + p * J_ * 12);
        #pragma unroll
        for (int j = 0; j < J_; ++j) {
            float2 wv = *(const float2*)&ws_t[j * WSTR + 2 * tid];
            unsigned long long wA = pack2s(wv.x);
            unsigned long long wB = pack2s(wv.y);
            const ulonglong2* trow = tbase + j * 6;   // 12 float2 = 6 x 16B
            #pragma unroll
            for (int m = 0; m < 6; ++m) {
                ulonglong2 q = trow[m];
                fma2acc(MA[2*m],     q.x, wA);
                fma2acc(MA[2*m + 1], q.y, wA);
                fma2acc(MB[2*m],     q.x, wB);
                fma2acc(MB[2*m + 1], q.y, wB);
            }
        }

        // Apply blended transform to both vertices; results per row are
        // packed {b0, b1}.
        float a0x, a1x, a0y, a1y, a0z, a1z;   // vertex A rows
        float b0x, b1x, b0y, b1y, b0z, b1z;   // vertex B rows
        {
            unsigned long long o;
            o = fma2(MA[2], ppzA, MA[3]); o = fma2(MA[1], ppyA, o); o = fma2(MA[0], ppxA, o);
            unpack2(o, a0x, a1x);
            o = fma2(MA[6], ppzA, MA[7]); o = fma2(MA[5], ppyA, o); o = fma2(MA[4], ppxA, o);
            unpack2(o, a0y, a1y);
            o = fma2(MA[10], ppzA, MA[11]); o = fma2(MA[9], ppyA, o); o = fma2(MA[8], ppxA, o);
            unpack2(o, a0z, a1z);
            o = fma2(MB[2], ppzB, MB[3]); o = fma2(MB[1], ppyB, o); o = fma2(MB[0], ppxB, o);
            unpack2(o, b0x, b1x);
            o = fma2(MB[6], ppzB, MB[7]); o = fma2(MB[5], ppyB, o); o = fma2(MB[4], ppxB, o);
            unpack2(o, b0y, b1y);
            o = fma2(MB[10], ppzB, MB[11]); o = fma2(MB[9], ppyB, o); o = fma2(MB[8], ppxB, o);
            unpack2(o, b0z, b1z);
        }

        // Store: 6 consecutive floats per batch, 3x STG.64
        *(float2*)(mesh_out + o0)     = make_float2(a0x, a0y);
        *(float2*)(mesh_out + o0 + 2) = make_float2(a0z, b0x);
        *(float2*)(mesh_out + o0 + 4) = make_float2(b0y, b0z);
        *(float2*)(mesh_out + o1)     = make_float2(a1x, a1y);
        *(float2*)(mesh_out + o1 + 2) = make_float2(a1z, b1x);
        *(float2*)(mesh_out + o1 + 4) = make_float2(b1y, b1z);
    }
}

// ---------------------------------------------------------------------------
extern "C" void kernel_launch(void* const* d_in, const int* in_sizes, int n_in,
                              void* d_out, int out_size) {
    const float* joint_euler = (const float*)d_in[0];
    const float* vtx         = (const float*)d_in[1];
    const float* W           = (const float*)d_in[2];
    const float* local_pose  = (const float*)d_in[3];
    const float* gpi         = (const float*)d_in[4];
    const float* sc          = (const float*)d_in[5];
    const float* pc          = (const float*)d_in[6];
    const float* ic          = (const float*)d_in[7];
    const int*   parents     = (const int*)d_in[8];
    float* out = (float*)d_out;

    fk_kernel<<<B_ / BPB, 1024>>>(joint_euler, local_pose, sc, gpi, parents, out);
    dim3 grid((V_ + VT2 - 1) / VT2, B_ / NB);
    skin_kernel<<<grid, VT>>>(vtx, W, pc, ic, out + B_*J_*3);
}